// round 15
// baseline (speedup 1.0000x reference)
#include <cuda_runtime.h>
#include <cuda_fp16.h>
#include <cstdint>

#define N_NODES 50000
#define E_MAX   800000
#define SCAN_CHUNK 4096
#define NB_SCAN ((N_NODES + SCAN_CHUNK - 1) / SCAN_CHUNK)   // 13

// ---- scratch (static __device__ — no allocations allowed) ----
__device__ __align__(16) __half g_xh  [N_NODES * 128];  // x in fp16
__device__ __align__(16) __half g_aggh[N_NODES * 128];  // MEAN of x[src] per dst (fp16)
__device__ __align__(16) __half g_ph  [N_NODES * 128];  // h @ W2_l.T  (fp16)
__device__ __align__(16) __half g_r2h [N_NODES * 128];  // h @ W2_r.T  (fp16)
__device__ __align__(16) __half g_W1h [256 * 256];      // [t][k] fp16
__device__ __align__(16) __half g_W2h [256 * 256];      // [j][k] fp16
// CSR by dst
__device__ __align__(16) int g_cnt [N_NODES];
__device__ int g_fill[N_NODES];
__device__ int g_rowptr[N_NODES + 1];
__device__ int g_eidx[E_MAX];
__device__ volatile int g_bpub[NB_SCAN];   // decoupled-scan flags: total+1, 0 = not ready

// ================= fused prep: zero cnt/flags + x->fp16 + weights->fp16 =================
#define PREP_TOTAL (N_NODES * 32 + N_NODES + 256 * 256 + NB_SCAN)
__global__ void prep_all(const float4* __restrict__ x,
                         const float* __restrict__ W1l, const float* __restrict__ W1r,
                         const float* __restrict__ W2l, const float* __restrict__ W2r) {
    int i = blockIdx.x * blockDim.x + threadIdx.x;
    if (i < N_NODES * 32) {
        float4 v = x[i];
        __half2* d = (__half2*)(g_xh + i * 4);
        d[0] = __floats2half2_rn(v.x, v.y);
        d[1] = __floats2half2_rn(v.z, v.w);
        return;
    }
    int j = i - N_NODES * 32;
    if (j < N_NODES) { g_cnt[j] = 0; return; }
    int w = j - N_NODES;
    if (w < 256 * 256) {
        int n = w >> 8, k = w & 255;
        g_W1h[w] = __float2half_rn((k < 128) ? W1l[n * 128 + k] : W1r[n * 128 + (k - 128)]);
        g_W2h[w] = __float2half_rn((n < 128) ? W2l[n * 256 + k] : W2r[(n - 128) * 256 + k]);
        return;
    }
    int f = w - 256 * 256;
    if (f < NB_SCAN) g_bpub[f] = 0;
}

// ================= CSR build =================
// 4 edges / thread: int4 index loads, 4 independent atomic chains (MLP=4)
__global__ void hist_kernel(const int* __restrict__ ei, int E) {
    int t = blockIdx.x * blockDim.x + threadIdx.x;
    int e4 = t * 4;
    if (e4 + 3 < E) {
        int4 d = *(const int4*)(ei + E + e4);
        atomicAdd(&g_cnt[d.x], 1);
        atomicAdd(&g_cnt[d.y], 1);
        atomicAdd(&g_cnt[d.z], 1);
        atomicAdd(&g_cnt[d.w], 1);
    } else {
        for (int e = e4; e < E; e++) atomicAdd(&g_cnt[ei[E + e]], 1);
    }
}

// single-pass scan: block-local scan + decoupled publish/spin (13 blocks, all co-resident)
__global__ __launch_bounds__(1024) void scan_all(int E) {
    __shared__ int wsum[32];
    __shared__ int s_off;
    int t = threadIdx.x, lane = t & 31, wid = t >> 5;
    int b = blockIdx.x;
    int base = b * SCAN_CHUNK + t * 4;
    int v0 = 0, v1 = 0, v2 = 0, v3 = 0;
    if (base + 3 < N_NODES) {
        int4 v = *(const int4*)(g_cnt + base);
        v0 = v.x; v1 = v.y; v2 = v.z; v3 = v.w;
    } else {
        if (base + 0 < N_NODES) v0 = g_cnt[base + 0];
        if (base + 1 < N_NODES) v1 = g_cnt[base + 1];
        if (base + 2 < N_NODES) v2 = g_cnt[base + 2];
        if (base + 3 < N_NODES) v3 = g_cnt[base + 3];
    }
    int s = v0 + v1 + v2 + v3;
    int inc = s;
#pragma unroll
    for (int off = 1; off < 32; off <<= 1) {
        int n = __shfl_up_sync(0xffffffff, inc, off);
        if (lane >= off) inc += n;
    }
    if (lane == 31) wsum[wid] = inc;
    __syncthreads();
    if (wid == 0) {
        int w = wsum[lane];
#pragma unroll
        for (int off = 1; off < 32; off <<= 1) {
            int n = __shfl_up_sync(0xffffffff, w, off);
            if (lane >= off) w += n;
        }
        wsum[lane] = w;
    }
    __syncthreads();
    int total = wsum[31];
    if (t == 0) g_bpub[b] = total + 1;          // publish (volatile store)
    if (wid == 0) {
        int v = 0;
        if (lane < b) {
            int p;
            while ((p = g_bpub[lane]) == 0) {}
            v = p - 1;
        }
#pragma unroll
        for (int off = 16; off > 0; off >>= 1)
            v += __shfl_xor_sync(0xffffffff, v, off);
        if (lane == 0) s_off = v;
    }
    __syncthreads();
    int goff = s_off;
    int excl = inc - s + (wid > 0 ? wsum[wid - 1] : 0) + goff;
    if (base + 0 < N_NODES) { g_rowptr[base + 0] = excl; g_fill[base + 0] = excl; } excl += v0;
    if (base + 1 < N_NODES) { g_rowptr[base + 1] = excl; g_fill[base + 1] = excl; } excl += v1;
    if (base + 2 < N_NODES) { g_rowptr[base + 2] = excl; g_fill[base + 2] = excl; } excl += v2;
    if (base + 3 < N_NODES) { g_rowptr[base + 3] = excl; g_fill[base + 3] = excl; }
    if (b == NB_SCAN - 1 && t == 0) g_rowptr[N_NODES] = E;
}

__global__ void fill_kernel(const int* __restrict__ ei, int E) {
    int t = blockIdx.x * blockDim.x + threadIdx.x;
    int e4 = t * 4;
    if (e4 + 3 < E) {
        int4 sv = *(const int4*)(ei + e4);
        int4 dv = *(const int4*)(ei + E + e4);
        int p0 = atomicAdd(&g_fill[dv.x], 1);
        int p1 = atomicAdd(&g_fill[dv.y], 1);
        int p2 = atomicAdd(&g_fill[dv.z], 1);
        int p3 = atomicAdd(&g_fill[dv.w], 1);
        g_eidx[p0] = sv.x;
        g_eidx[p1] = sv.y;
        g_eidx[p2] = sv.z;
        g_eidx[p3] = sv.w;
    } else {
        for (int e = e4; e < E; e++) {
            int pos = atomicAdd(&g_fill[ei[E + e]], 1);
            g_eidx[pos] = ei[e];
        }
    }
}

// ================= gather-side aggregation (fp16 payload, fp32 accum) =================
__device__ __forceinline__ void acc_u2(float4& acc, uint2 u) {
    float2 f0 = __half22float2(*(__half2*)&u.x);
    float2 f1 = __half22float2(*(__half2*)&u.y);
    acc.x += f0.x; acc.y += f0.y; acc.z += f1.x; acc.w += f1.y;
}

template <int FINAL>
__global__ void agg_gather(const float* __restrict__ b2, float4* __restrict__ out) {
    int node = blockIdx.x * 8 + (threadIdx.x >> 5);
    int lane = threadIdx.x & 31;
    if (node >= N_NODES) return;
    int row = g_rowptr[node], end = g_rowptr[node + 1];
    const uint2* feat = (const uint2*)(FINAL ? g_ph : g_xh);   // [node*32 + lane]
    float4 acc = make_float4(0.f, 0.f, 0.f, 0.f);
    int j = row;
    for (; j + 4 <= end; j += 4) {
        int s0 = __ldg(g_eidx + j), s1 = __ldg(g_eidx + j + 1);
        int s2 = __ldg(g_eidx + j + 2), s3 = __ldg(g_eidx + j + 3);
        acc_u2(acc, feat[s0 * 32 + lane]);
        acc_u2(acc, feat[s1 * 32 + lane]);
        acc_u2(acc, feat[s2 * 32 + lane]);
        acc_u2(acc, feat[s3 * 32 + lane]);
    }
    for (; j < end; j++) {
        int s = __ldg(g_eidx + j);
        acc_u2(acc, feat[s * 32 + lane]);
    }
    float invd = 1.0f / fmaxf((float)(end - row), 1.0f);
    acc.x *= invd; acc.y *= invd; acc.z *= invd; acc.w *= invd;
    if (FINAL) {
        uint2 ru = ((const uint2*)g_r2h)[node * 32 + lane];
        float2 r0 = __half22float2(*(__half2*)&ru.x);
        float2 r1 = __half22float2(*(__half2*)&ru.y);
        float4 bb = ((const float4*)b2)[lane];
        float4 o;
        o.x = acc.x + bb.x + r0.x;
        o.y = acc.y + bb.y + r0.y;
        o.z = acc.z + bb.z + r1.x;
        o.w = acc.w + bb.w + r1.y;
        out[node * 32 + lane] = o;
    } else {
        __half2* d = (__half2*)(g_aggh + node * 128 + lane * 4);
        d[0] = __floats2half2_rn(acc.x, acc.y);
        d[1] = __floats2half2_rn(acc.z, acc.w);
    }
}

// ================= FP16 tensor-core fused double-GEMM =================
#define SA_H 264
#define SB_H 72
#define SA_HALFS (64 * SA_H)
#define SB_HALFS (256 * SB_H)
#define SMEM_BYTES ((SA_HALFS + 2 * SB_HALFS) * 2)

__device__ __forceinline__ void cp16h(__half* dst, const __half* src) {
    uint32_t sa = (uint32_t)__cvta_generic_to_shared(dst);
    asm volatile("cp.async.ca.shared.global [%0], [%1], 16;" :: "r"(sa), "l"(src));
}
__device__ __forceinline__ void cp_commit() { asm volatile("cp.async.commit_group;"); }
__device__ __forceinline__ void cp_wait0()  { asm volatile("cp.async.wait_group 0;"); }

__device__ __forceinline__ void load_chunkB(__half* buf, const __half* Wg, int kc, int tid) {
#pragma unroll
    for (int i = 0; i < 8; i++) {
        int idx = tid + i * 256;
        int n = idx >> 3, c8 = idx & 7;
        cp16h(buf + n * SB_H + c8 * 8, Wg + n * 256 + kc * 64 + c8 * 8);
    }
}

__device__ __forceinline__ void mma_f16(float* d, uint32_t a0, uint32_t a1, uint32_t a2,
                                        uint32_t a3, uint32_t b0, uint32_t b1) {
    asm volatile(
        "mma.sync.aligned.m16n8k16.row.col.f32.f16.f16.f32 "
        "{%0,%1,%2,%3}, {%4,%5,%6,%7}, {%8,%9}, {%0,%1,%2,%3};"
        : "+f"(d[0]), "+f"(d[1]), "+f"(d[2]), "+f"(d[3])
        : "r"(a0), "r"(a1), "r"(a2), "r"(a3), "r"(b0), "r"(b1));
}

// one 256-K fp16 GEMM: acc += A(64x256 smem) @ Wg(256n x 256k, row=n)^T
__device__ __forceinline__ void gemm_fp16(const __half* A, const __half* Wg, const __half* WgNext,
                                          __half* sB0, __half* sB1,
                                          float acc[4][4][4], int tid, int lane, int n_base) {
    __half* sb[2] = {sB0, sB1};
    for (int kc = 0; kc < 4; kc++) {
        cp_wait0();
        __syncthreads();
        if (kc < 3)      { load_chunkB(sb[(kc + 1) & 1], Wg, kc + 1, tid); cp_commit(); }
        else if (WgNext) { load_chunkB(sb[0], WgNext, 0, tid); cp_commit(); }
        const __half* B = sb[kc & 1];
#pragma unroll
        for (int ksl = 0; ksl < 4; ksl++) {
            uint32_t bf[4][2];
#pragma unroll
            for (int np = 0; np < 2; np++) {
                int n = n_base + np * 16 + ((lane >> 4) << 3) + (lane & 7);
                int kl = ksl * 16 + ((lane >> 3) & 1) * 8;
                uint32_t ad = (uint32_t)__cvta_generic_to_shared(B + n * SB_H + kl);
                asm volatile("ldmatrix.sync.aligned.m8n8.x4.shared.b16 {%0,%1,%2,%3}, [%4];"
                             : "=r"(bf[np * 2][0]), "=r"(bf[np * 2][1]),
                               "=r"(bf[np * 2 + 1][0]), "=r"(bf[np * 2 + 1][1]) : "r"(ad));
            }
#pragma unroll
            for (int mt = 0; mt < 4; mt++) {
                int m = mt * 16 + (lane & 15);
                int kk = kc * 64 + ksl * 16 + (lane >> 4) * 8;
                uint32_t ad = (uint32_t)__cvta_generic_to_shared(A + m * SA_H + kk);
                uint32_t a0, a1, a2, a3;
                asm volatile("ldmatrix.sync.aligned.m8n8.x4.shared.b16 {%0,%1,%2,%3}, [%4];"
                             : "=r"(a0), "=r"(a1), "=r"(a2), "=r"(a3) : "r"(ad));
#pragma unroll
                for (int nt = 0; nt < 4; nt++)
                    mma_f16(acc[mt][nt], a0, a1, a2, a3, bf[nt][0], bf[nt][1]);
            }
        }
    }
}

__global__ __launch_bounds__(256, 2) void gemm_mma_h(const float* __restrict__ b1) {
    extern __shared__ __half smem_h[];
    __half* sA  = smem_h;
    __half* sB0 = smem_h + SA_HALFS;
    __half* sB1 = sB0 + SB_HALFS;

    int tid = threadIdx.x, lane = tid & 31, warp = tid >> 5;
    int node0 = blockIdx.x * 64;
    int n_base = warp * 32;

    load_chunkB(sB0, g_W1h, 0, tid);
#pragma unroll
    for (int i = 0; i < 8; i++) {
        int idx = tid + i * 256;
        int n = idx >> 5, c8 = idx & 31;
        int node = node0 + n;
        if (node >= N_NODES) node = N_NODES - 1;
        const __half* src = (c8 < 16) ? (g_aggh + node * 128 + c8 * 8)
                                      : (g_xh  + node * 128 + (c8 - 16) * 8);
        cp16h(sA + n * SA_H + c8 * 8, src);
    }
    cp_commit();

    float acc[4][4][4];
#pragma unroll
    for (int a = 0; a < 4; a++)
#pragma unroll
        for (int b = 0; b < 4; b++)
#pragma unroll
            for (int c = 0; c < 4; c++) acc[a][b][c] = 0.f;

    gemm_fp16(sA, g_W1h, g_W2h, sB0, sB1, acc, tid, lane, n_base);

    __syncthreads();

#pragma unroll
    for (int mt = 0; mt < 4; mt++) {
        int row = mt * 16 + (lane >> 2);
#pragma unroll
        for (int nt = 0; nt < 4; nt++) {
            int col = n_base + nt * 8 + (lane & 3) * 2;
            float bb0 = __ldg(b1 + col), bb1 = __ldg(b1 + col + 1);
            *(__half2*)(sA + row * SA_H + col) =
                __floats2half2_rn(fmaxf(acc[mt][nt][0] + bb0, 0.f),
                                  fmaxf(acc[mt][nt][1] + bb1, 0.f));
            *(__half2*)(sA + (row + 8) * SA_H + col) =
                __floats2half2_rn(fmaxf(acc[mt][nt][2] + bb0, 0.f),
                                  fmaxf(acc[mt][nt][3] + bb1, 0.f));
            acc[mt][nt][0] = acc[mt][nt][1] = acc[mt][nt][2] = acc[mt][nt][3] = 0.f;
        }
    }

    gemm_fp16(sA, g_W2h, nullptr, sB0, sB1, acc, tid, lane, n_base);

    // store p (cols<128) and r2 (cols>=128) as fp16
#pragma unroll
    for (int mt = 0; mt < 4; mt++) {
        int row = mt * 16 + (lane >> 2);
#pragma unroll
        for (int nt = 0; nt < 4; nt++) {
            int col = n_base + nt * 8 + (lane & 3) * 2;
            int node = node0 + row;
            __half* base = (col < 128) ? g_ph : g_r2h;
            int cc = col & 127;
            if (node < N_NODES)
                *(__half2*)(base + node * 128 + cc) =
                    __floats2half2_rn(acc[mt][nt][0], acc[mt][nt][1]);
            if (node + 8 < N_NODES)
                *(__half2*)(base + (node + 8) * 128 + cc) =
                    __floats2half2_rn(acc[mt][nt][2], acc[mt][nt][3]);
        }
    }
}

extern "C" void kernel_launch(void* const* d_in, const int* in_sizes, int n_in,
                              void* d_out, int out_size) {
    const float4* x   = (const float4*)d_in[0];
    const int*    ei  = (const int*)d_in[1];
    const float*  W1l = (const float*)d_in[2];
    const float*  b1  = (const float*)d_in[3];
    const float*  W1r = (const float*)d_in[4];
    const float*  W2l = (const float*)d_in[5];
    const float*  b2  = (const float*)d_in[6];
    const float*  W2r = (const float*)d_in[7];
    int E = in_sizes[1] / 2;
    int E4 = (E + 3) / 4;

    cudaFuncSetAttribute(gemm_mma_h, cudaFuncAttributeMaxDynamicSharedMemorySize, SMEM_BYTES);

    prep_all<<<(PREP_TOTAL + 255) / 256, 256>>>(x, W1l, W1r, W2l, W2r);
    hist_kernel<<<(E4 + 255) / 256, 256>>>(ei, E);
    scan_all<<<NB_SCAN, 1024>>>(E);
    fill_kernel<<<(E4 + 255) / 256, 256>>>(ei, E);
    agg_gather<0><<<(N_NODES + 7) / 8, 256>>>(nullptr, nullptr);
    gemm_mma_h<<<(N_NODES + 63) / 64, 256, SMEM_BYTES>>>(b1);
    agg_gather<1><<<(N_NODES + 7) / 8, 256>>>(b2, (float4*)d_out);
}

// round 16
// speedup vs baseline: 1.0321x; 1.0321x over previous
#include <cuda_runtime.h>
#include <cuda_fp16.h>
#include <cstdint>

#define N_NODES 50000
#define E_MAX   800000
#define SCAN_CHUNK 4096
#define NB_SCAN ((N_NODES + SCAN_CHUNK - 1) / SCAN_CHUNK)   // 13

// ---- scratch (static __device__ — no allocations; zero-init at load) ----
__device__ __align__(16) __half g_xh  [N_NODES * 128];  // x in fp16
__device__ __align__(16) __half g_aggh[N_NODES * 128];  // MEAN of x[src] per dst (fp16)
__device__ __align__(16) __half g_ph  [N_NODES * 128];  // h @ W2_l.T  (fp16)
__device__ __align__(16) __half g_r2h [N_NODES * 128];  // h @ W2_r.T  (fp16)
__device__ __align__(16) __half g_W1h [256 * 256];      // [t][k] fp16
__device__ __align__(16) __half g_W2h [256 * 256];      // [j][k] fp16
// CSR by dst (g_cnt/g_bpub are re-zeroed by fill_kernel each iteration)
__device__ __align__(16) int g_cnt [N_NODES];
__device__ int g_fill[N_NODES];
__device__ int g_rowptr[N_NODES + 1];
__device__ int g_eidx[E_MAX];
__device__ volatile int g_bpub[NB_SCAN];   // decoupled-scan flags: total+1, 0 = not ready

// ===== fused prep: x->fp16 + weights->fp16 + dst histogram (g_cnt pre-zeroed) =====
__global__ void prep_all(const float4* __restrict__ x,
                         const float* __restrict__ W1l, const float* __restrict__ W1r,
                         const float* __restrict__ W2l, const float* __restrict__ W2r,
                         const int* __restrict__ ei, int E) {
    int i = blockIdx.x * blockDim.x + threadIdx.x;
    if (i < N_NODES * 32) {
        float4 v = x[i];
        __half2* d = (__half2*)(g_xh + i * 4);
        d[0] = __floats2half2_rn(v.x, v.y);
        d[1] = __floats2half2_rn(v.z, v.w);
        return;
    }
    int w = i - N_NODES * 32;
    if (w < 256 * 256) {
        int n = w >> 8, k = w & 255;
        g_W1h[w] = __float2half_rn((k < 128) ? W1l[n * 128 + k] : W1r[n * 128 + (k - 128)]);
        g_W2h[w] = __float2half_rn((n < 128) ? W2l[n * 256 + k] : W2r[(n - 128) * 256 + k]);
        return;
    }
    int e = w - 256 * 256;
    if (e < E) atomicAdd(&g_cnt[ei[E + e]], 1);
}

// single-pass scan: block-local scan + decoupled publish/spin (13 blocks, all co-resident)
__global__ __launch_bounds__(1024) void scan_all(int E) {
    __shared__ int wsum[32];
    __shared__ int s_off;
    int t = threadIdx.x, lane = t & 31, wid = t >> 5;
    int b = blockIdx.x;
    int base = b * SCAN_CHUNK + t * 4;
    int v0 = 0, v1 = 0, v2 = 0, v3 = 0;
    if (base + 3 < N_NODES) {
        int4 v = *(const int4*)(g_cnt + base);
        v0 = v.x; v1 = v.y; v2 = v.z; v3 = v.w;
    } else {
        if (base + 0 < N_NODES) v0 = g_cnt[base + 0];
        if (base + 1 < N_NODES) v1 = g_cnt[base + 1];
        if (base + 2 < N_NODES) v2 = g_cnt[base + 2];
        if (base + 3 < N_NODES) v3 = g_cnt[base + 3];
    }
    int s = v0 + v1 + v2 + v3;
    int inc = s;
#pragma unroll
    for (int off = 1; off < 32; off <<= 1) {
        int n = __shfl_up_sync(0xffffffff, inc, off);
        if (lane >= off) inc += n;
    }
    if (lane == 31) wsum[wid] = inc;
    __syncthreads();
    if (wid == 0) {
        int w = wsum[lane];
#pragma unroll
        for (int off = 1; off < 32; off <<= 1) {
            int n = __shfl_up_sync(0xffffffff, w, off);
            if (lane >= off) w += n;
        }
        wsum[lane] = w;
    }
    __syncthreads();
    int total = wsum[31];
    if (t == 0) g_bpub[b] = total + 1;          // publish (volatile store)
    if (wid == 0) {
        int v = 0;
        if (lane < b) {
            int p;
            while ((p = g_bpub[lane]) == 0) {}
            v = p - 1;
        }
#pragma unroll
        for (int off = 16; off > 0; off >>= 1)
            v += __shfl_xor_sync(0xffffffff, v, off);
        if (lane == 0) s_off = v;
    }
    __syncthreads();
    int goff = s_off;
    int excl = inc - s + (wid > 0 ? wsum[wid - 1] : 0) + goff;
    if (base + 0 < N_NODES) { g_rowptr[base + 0] = excl; g_fill[base + 0] = excl; } excl += v0;
    if (base + 1 < N_NODES) { g_rowptr[base + 1] = excl; g_fill[base + 1] = excl; } excl += v1;
    if (base + 2 < N_NODES) { g_rowptr[base + 2] = excl; g_fill[base + 2] = excl; } excl += v2;
    if (base + 3 < N_NODES) { g_rowptr[base + 3] = excl; g_fill[base + 3] = excl; }
    if (b == NB_SCAN - 1 && t == 0) g_rowptr[N_NODES] = E;
}

// fill CSR + re-zero g_cnt/g_bpub for the NEXT launch (both already consumed by scan_all)
__global__ void fill_kernel(const int* __restrict__ ei, int E) {
    int e = blockIdx.x * blockDim.x + threadIdx.x;
    if (e < N_NODES) g_cnt[e] = 0;
    if (e < NB_SCAN) g_bpub[e] = 0;
    if (e >= E) return;
    int s = ei[e];
    int d = ei[E + e];
    int pos = atomicAdd(&g_fill[d], 1);
    g_eidx[pos] = s;
}

// ================= gather-side aggregation (fp16 payload, fp32 accum) =================
__device__ __forceinline__ void acc_u2(float4& acc, uint2 u) {
    float2 f0 = __half22float2(*(__half2*)&u.x);
    float2 f1 = __half22float2(*(__half2*)&u.y);
    acc.x += f0.x; acc.y += f0.y; acc.z += f1.x; acc.w += f1.y;
}

template <int FINAL>
__global__ void agg_gather(const float* __restrict__ b2, float4* __restrict__ out) {
    int node = blockIdx.x * 8 + (threadIdx.x >> 5);
    int lane = threadIdx.x & 31;
    if (node >= N_NODES) return;
    int row = g_rowptr[node], end = g_rowptr[node + 1];
    const uint2* feat = (const uint2*)(FINAL ? g_ph : g_xh);   // [node*32 + lane]
    float4 acc = make_float4(0.f, 0.f, 0.f, 0.f);
    int j = row;
    for (; j + 4 <= end; j += 4) {
        int s0 = __ldg(g_eidx + j), s1 = __ldg(g_eidx + j + 1);
        int s2 = __ldg(g_eidx + j + 2), s3 = __ldg(g_eidx + j + 3);
        acc_u2(acc, feat[s0 * 32 + lane]);
        acc_u2(acc, feat[s1 * 32 + lane]);
        acc_u2(acc, feat[s2 * 32 + lane]);
        acc_u2(acc, feat[s3 * 32 + lane]);
    }
    for (; j < end; j++) {
        int s = __ldg(g_eidx + j);
        acc_u2(acc, feat[s * 32 + lane]);
    }
    float invd = 1.0f / fmaxf((float)(end - row), 1.0f);
    acc.x *= invd; acc.y *= invd; acc.z *= invd; acc.w *= invd;
    if (FINAL) {
        uint2 ru = ((const uint2*)g_r2h)[node * 32 + lane];
        float2 r0 = __half22float2(*(__half2*)&ru.x);
        float2 r1 = __half22float2(*(__half2*)&ru.y);
        float4 bb = ((const float4*)b2)[lane];
        float4 o;
        o.x = acc.x + bb.x + r0.x;
        o.y = acc.y + bb.y + r0.y;
        o.z = acc.z + bb.z + r1.x;
        o.w = acc.w + bb.w + r1.y;
        out[node * 32 + lane] = o;
    } else {
        __half2* d = (__half2*)(g_aggh + node * 128 + lane * 4);
        d[0] = __floats2half2_rn(acc.x, acc.y);
        d[1] = __floats2half2_rn(acc.z, acc.w);
    }
}

// ================= FP16 tensor-core fused double-GEMM =================
#define SA_H 264
#define SB_H 72
#define SA_HALFS (64 * SA_H)
#define SB_HALFS (256 * SB_H)
#define SMEM_BYTES ((SA_HALFS + 2 * SB_HALFS) * 2)

__device__ __forceinline__ void cp16h(__half* dst, const __half* src) {
    uint32_t sa = (uint32_t)__cvta_generic_to_shared(dst);
    asm volatile("cp.async.ca.shared.global [%0], [%1], 16;" :: "r"(sa), "l"(src));
}
__device__ __forceinline__ void cp_commit() { asm volatile("cp.async.commit_group;"); }
__device__ __forceinline__ void cp_wait0()  { asm volatile("cp.async.wait_group 0;"); }

__device__ __forceinline__ void load_chunkB(__half* buf, const __half* Wg, int kc, int tid) {
#pragma unroll
    for (int i = 0; i < 8; i++) {
        int idx = tid + i * 256;
        int n = idx >> 3, c8 = idx & 7;
        cp16h(buf + n * SB_H + c8 * 8, Wg + n * 256 + kc * 64 + c8 * 8);
    }
}

__device__ __forceinline__ void mma_f16(float* d, uint32_t a0, uint32_t a1, uint32_t a2,
                                        uint32_t a3, uint32_t b0, uint32_t b1) {
    asm volatile(
        "mma.sync.aligned.m16n8k16.row.col.f32.f16.f16.f32 "
        "{%0,%1,%2,%3}, {%4,%5,%6,%7}, {%8,%9}, {%0,%1,%2,%3};"
        : "+f"(d[0]), "+f"(d[1]), "+f"(d[2]), "+f"(d[3])
        : "r"(a0), "r"(a1), "r"(a2), "r"(a3), "r"(b0), "r"(b1));
}

// one 256-K fp16 GEMM: acc += A(64x256 smem) @ Wg(256n x 256k, row=n)^T
__device__ __forceinline__ void gemm_fp16(const __half* A, const __half* Wg, const __half* WgNext,
                                          __half* sB0, __half* sB1,
                                          float acc[4][4][4], int tid, int lane, int n_base) {
    __half* sb[2] = {sB0, sB1};
    for (int kc = 0; kc < 4; kc++) {
        cp_wait0();
        __syncthreads();
        if (kc < 3)      { load_chunkB(sb[(kc + 1) & 1], Wg, kc + 1, tid); cp_commit(); }
        else if (WgNext) { load_chunkB(sb[0], WgNext, 0, tid); cp_commit(); }
        const __half* B = sb[kc & 1];
#pragma unroll
        for (int ksl = 0; ksl < 4; ksl++) {
            uint32_t bf[4][2];
#pragma unroll
            for (int np = 0; np < 2; np++) {
                int n = n_base + np * 16 + ((lane >> 4) << 3) + (lane & 7);
                int kl = ksl * 16 + ((lane >> 3) & 1) * 8;
                uint32_t ad = (uint32_t)__cvta_generic_to_shared(B + n * SB_H + kl);
                asm volatile("ldmatrix.sync.aligned.m8n8.x4.shared.b16 {%0,%1,%2,%3}, [%4];"
                             : "=r"(bf[np * 2][0]), "=r"(bf[np * 2][1]),
                               "=r"(bf[np * 2 + 1][0]), "=r"(bf[np * 2 + 1][1]) : "r"(ad));
            }
#pragma unroll
            for (int mt = 0; mt < 4; mt++) {
                int m = mt * 16 + (lane & 15);
                int kk = kc * 64 + ksl * 16 + (lane >> 4) * 8;
                uint32_t ad = (uint32_t)__cvta_generic_to_shared(A + m * SA_H + kk);
                uint32_t a0, a1, a2, a3;
                asm volatile("ldmatrix.sync.aligned.m8n8.x4.shared.b16 {%0,%1,%2,%3}, [%4];"
                             : "=r"(a0), "=r"(a1), "=r"(a2), "=r"(a3) : "r"(ad));
#pragma unroll
                for (int nt = 0; nt < 4; nt++)
                    mma_f16(acc[mt][nt], a0, a1, a2, a3, bf[nt][0], bf[nt][1]);
            }
        }
    }
}

__global__ __launch_bounds__(256, 2) void gemm_mma_h(const float* __restrict__ b1) {
    extern __shared__ __half smem_h[];
    __half* sA  = smem_h;
    __half* sB0 = smem_h + SA_HALFS;
    __half* sB1 = sB0 + SB_HALFS;

    int tid = threadIdx.x, lane = tid & 31, warp = tid >> 5;
    int node0 = blockIdx.x * 64;
    int n_base = warp * 32;

    load_chunkB(sB0, g_W1h, 0, tid);
#pragma unroll
    for (int i = 0; i < 8; i++) {
        int idx = tid + i * 256;
        int n = idx >> 5, c8 = idx & 31;
        int node = node0 + n;
        if (node >= N_NODES) node = N_NODES - 1;
        const __half* src = (c8 < 16) ? (g_aggh + node * 128 + c8 * 8)
                                      : (g_xh  + node * 128 + (c8 - 16) * 8);
        cp16h(sA + n * SA_H + c8 * 8, src);
    }
    cp_commit();

    float acc[4][4][4];
#pragma unroll
    for (int a = 0; a < 4; a++)
#pragma unroll
        for (int b = 0; b < 4; b++)
#pragma unroll
            for (int c = 0; c < 4; c++) acc[a][b][c] = 0.f;

    gemm_fp16(sA, g_W1h, g_W2h, sB0, sB1, acc, tid, lane, n_base);

    __syncthreads();

#pragma unroll
    for (int mt = 0; mt < 4; mt++) {
        int row = mt * 16 + (lane >> 2);
#pragma unroll
        for (int nt = 0; nt < 4; nt++) {
            int col = n_base + nt * 8 + (lane & 3) * 2;
            float bb0 = __ldg(b1 + col), bb1 = __ldg(b1 + col + 1);
            *(__half2*)(sA + row * SA_H + col) =
                __floats2half2_rn(fmaxf(acc[mt][nt][0] + bb0, 0.f),
                                  fmaxf(acc[mt][nt][1] + bb1, 0.f));
            *(__half2*)(sA + (row + 8) * SA_H + col) =
                __floats2half2_rn(fmaxf(acc[mt][nt][2] + bb0, 0.f),
                                  fmaxf(acc[mt][nt][3] + bb1, 0.f));
            acc[mt][nt][0] = acc[mt][nt][1] = acc[mt][nt][2] = acc[mt][nt][3] = 0.f;
        }
    }

    gemm_fp16(sA, g_W2h, nullptr, sB0, sB1, acc, tid, lane, n_base);

    // store p (cols<128) and r2 (cols>=128) as fp16
#pragma unroll
    for (int mt = 0; mt < 4; mt++) {
        int row = mt * 16 + (lane >> 2);
#pragma unroll
        for (int nt = 0; nt < 4; nt++) {
            int col = n_base + nt * 8 + (lane & 3) * 2;
            int node = node0 + row;
            __half* base = (col < 128) ? g_ph : g_r2h;
            int cc = col & 127;
            if (node < N_NODES)
                *(__half2*)(base + node * 128 + cc) =
                    __floats2half2_rn(acc[mt][nt][0], acc[mt][nt][1]);
            if (node + 8 < N_NODES)
                *(__half2*)(base + (node + 8) * 128 + cc) =
                    __floats2half2_rn(acc[mt][nt][2], acc[mt][nt][3]);
        }
    }
}

extern "C" void kernel_launch(void* const* d_in, const int* in_sizes, int n_in,
                              void* d_out, int out_size) {
    const float4* x   = (const float4*)d_in[0];
    const int*    ei  = (const int*)d_in[1];
    const float*  W1l = (const float*)d_in[2];
    const float*  b1  = (const float*)d_in[3];
    const float*  W1r = (const float*)d_in[4];
    const float*  W2l = (const float*)d_in[5];
    const float*  b2  = (const float*)d_in[6];
    const float*  W2r = (const float*)d_in[7];
    int E = in_sizes[1] / 2;
    int prep_total = N_NODES * 32 + 256 * 256 + E;

    cudaFuncSetAttribute(gemm_mma_h, cudaFuncAttributeMaxDynamicSharedMemorySize, SMEM_BYTES);

    prep_all<<<(prep_total + 255) / 256, 256>>>(x, W1l, W1r, W2l, W2r, ei, E);
    scan_all<<<NB_SCAN, 1024>>>(E);
    fill_kernel<<<(E + 255) / 256, 256>>>(ei, E);
    agg_gather<0><<<(N_NODES + 7) / 8, 256>>>(nullptr, nullptr);
    gemm_mma_h<<<(N_NODES + 63) / 64, 256, SMEM_BYTES>>>(b1);
    agg_gather<1><<<(N_NODES + 7) / 8, 256>>>(b2, (float4*)d_out);
}

// round 17
// speedup vs baseline: 1.0847x; 1.0509x over previous
#include <cuda_runtime.h>
#include <cuda_fp16.h>
#include <cstdint>

#define N_NODES 50000
#define E_MAX   800000
#define SCAN_CHUNK 4096
#define NB_SCAN ((N_NODES + SCAN_CHUNK - 1) / SCAN_CHUNK)   // 13

// ---- scratch (static __device__ — no allocations; zero-init at load) ----
__device__ __align__(16) __half g_xh  [N_NODES * 128];  // x in fp16
__device__ __align__(16) __half g_aggh[N_NODES * 128];  // MEAN of x[src] per dst (fp16)
__device__ __align__(16) __half g_ph  [N_NODES * 128];  // h @ W2_l.T  (fp16)
__device__ __align__(16) __half g_r2h [N_NODES * 128];  // h @ W2_r.T  (fp16)
__device__ __align__(16) __half g_W1h [256 * 256];      // [t][k] fp16
__device__ __align__(16) __half g_W2h [256 * 256];      // [j][k] fp16
// CSR by dst (g_cnt/g_bpub are re-zeroed by fill_kernel each iteration)
__device__ __align__(16) int g_cnt [N_NODES];
__device__ int g_fill[N_NODES];
__device__ int g_rowptr[N_NODES + 1];
__device__ int g_eidx[E_MAX];
__device__ volatile int g_bpub[NB_SCAN];   // decoupled-scan flags: total+1, 0 = not ready

// ===== fused prep: x->fp16 + weights->fp16 + dst histogram (g_cnt pre-zeroed) =====
__global__ void prep_all(const float4* __restrict__ x,
                         const float* __restrict__ W1l, const float* __restrict__ W1r,
                         const float* __restrict__ W2l, const float* __restrict__ W2r,
                         const int* __restrict__ ei, int E) {
    int i = blockIdx.x * blockDim.x + threadIdx.x;
    if (i < N_NODES * 32) {
        float4 v = x[i];
        __half2* d = (__half2*)(g_xh + i * 4);
        d[0] = __floats2half2_rn(v.x, v.y);
        d[1] = __floats2half2_rn(v.z, v.w);
        return;
    }
    int w = i - N_NODES * 32;
    if (w < 256 * 256) {
        int n = w >> 8, k = w & 255;
        g_W1h[w] = __float2half_rn((k < 128) ? W1l[n * 128 + k] : W1r[n * 128 + (k - 128)]);
        g_W2h[w] = __float2half_rn((n < 128) ? W2l[n * 256 + k] : W2r[(n - 128) * 256 + k]);
        return;
    }
    int e = w - 256 * 256;
    if (e < E) atomicAdd(&g_cnt[ei[E + e]], 1);
}

// single-pass scan: block-local scan + decoupled publish/spin (13 blocks, all co-resident)
__global__ __launch_bounds__(1024) void scan_all(int E) {
    __shared__ int wsum[32];
    __shared__ int s_off;
    int t = threadIdx.x, lane = t & 31, wid = t >> 5;
    int b = blockIdx.x;
    int base = b * SCAN_CHUNK + t * 4;
    int v0 = 0, v1 = 0, v2 = 0, v3 = 0;
    if (base + 3 < N_NODES) {
        int4 v = *(const int4*)(g_cnt + base);
        v0 = v.x; v1 = v.y; v2 = v.z; v3 = v.w;
    } else {
        if (base + 0 < N_NODES) v0 = g_cnt[base + 0];
        if (base + 1 < N_NODES) v1 = g_cnt[base + 1];
        if (base + 2 < N_NODES) v2 = g_cnt[base + 2];
        if (base + 3 < N_NODES) v3 = g_cnt[base + 3];
    }
    int s = v0 + v1 + v2 + v3;
    int inc = s;
#pragma unroll
    for (int off = 1; off < 32; off <<= 1) {
        int n = __shfl_up_sync(0xffffffff, inc, off);
        if (lane >= off) inc += n;
    }
    if (lane == 31) wsum[wid] = inc;
    __syncthreads();
    if (wid == 0) {
        int w = wsum[lane];
#pragma unroll
        for (int off = 1; off < 32; off <<= 1) {
            int n = __shfl_up_sync(0xffffffff, w, off);
            if (lane >= off) w += n;
        }
        wsum[lane] = w;
    }
    __syncthreads();
    int total = wsum[31];
    if (t == 0) g_bpub[b] = total + 1;          // publish (volatile store)
    if (wid == 0) {
        int v = 0;
        if (lane < b) {
            int p;
            while ((p = g_bpub[lane]) == 0) {}
            v = p - 1;
        }
#pragma unroll
        for (int off = 16; off > 0; off >>= 1)
            v += __shfl_xor_sync(0xffffffff, v, off);
        if (lane == 0) s_off = v;
    }
    __syncthreads();
    int goff = s_off;
    int excl = inc - s + (wid > 0 ? wsum[wid - 1] : 0) + goff;
    if (base + 0 < N_NODES) { g_rowptr[base + 0] = excl; g_fill[base + 0] = excl; } excl += v0;
    if (base + 1 < N_NODES) { g_rowptr[base + 1] = excl; g_fill[base + 1] = excl; } excl += v1;
    if (base + 2 < N_NODES) { g_rowptr[base + 2] = excl; g_fill[base + 2] = excl; } excl += v2;
    if (base + 3 < N_NODES) { g_rowptr[base + 3] = excl; g_fill[base + 3] = excl; }
    if (b == NB_SCAN - 1 && t == 0) g_rowptr[N_NODES] = E;
}

// fill CSR + re-zero g_cnt/g_bpub for the NEXT launch (both already consumed by scan_all)
__global__ void fill_kernel(const int* __restrict__ ei, int E) {
    int e = blockIdx.x * blockDim.x + threadIdx.x;
    if (e < N_NODES) g_cnt[e] = 0;
    if (e < NB_SCAN) g_bpub[e] = 0;
    if (e >= E) return;
    int s = ei[e];
    int d = ei[E + e];
    int pos = atomicAdd(&g_fill[d], 1);
    g_eidx[pos] = s;
}

// ================= gather-side aggregation (fp16 payload, fp32 accum) =================
__device__ __forceinline__ void acc_u2(float4& acc, uint2 u) {
    float2 f0 = __half22float2(*(__half2*)&u.x);
    float2 f1 = __half22float2(*(__half2*)&u.y);
    acc.x += f0.x; acc.y += f0.y; acc.z += f1.x; acc.w += f1.y;
}

template <int FINAL>
__global__ void agg_gather(const float* __restrict__ b2, float4* __restrict__ out) {
    int node = blockIdx.x * 8 + (threadIdx.x >> 5);
    int lane = threadIdx.x & 31;
    if (node >= N_NODES) return;
    int row = g_rowptr[node], end = g_rowptr[node + 1];
    const uint2* feat = (const uint2*)(FINAL ? g_ph : g_xh);   // [node*32 + lane]
    float4 acc = make_float4(0.f, 0.f, 0.f, 0.f);
    int j = row;
    for (; j + 4 <= end; j += 4) {
        int s0 = __ldg(g_eidx + j), s1 = __ldg(g_eidx + j + 1);
        int s2 = __ldg(g_eidx + j + 2), s3 = __ldg(g_eidx + j + 3);
        acc_u2(acc, feat[s0 * 32 + lane]);
        acc_u2(acc, feat[s1 * 32 + lane]);
        acc_u2(acc, feat[s2 * 32 + lane]);
        acc_u2(acc, feat[s3 * 32 + lane]);
    }
    for (; j < end; j++) {
        int s = __ldg(g_eidx + j);
        acc_u2(acc, feat[s * 32 + lane]);
    }
    float invd = 1.0f / fmaxf((float)(end - row), 1.0f);
    acc.x *= invd; acc.y *= invd; acc.z *= invd; acc.w *= invd;
    if (FINAL) {
        uint2 ru = ((const uint2*)g_r2h)[node * 32 + lane];
        float2 r0 = __half22float2(*(__half2*)&ru.x);
        float2 r1 = __half22float2(*(__half2*)&ru.y);
        float4 bb = ((const float4*)b2)[lane];
        float4 o;
        o.x = acc.x + bb.x + r0.x;
        o.y = acc.y + bb.y + r0.y;
        o.z = acc.z + bb.z + r1.x;
        o.w = acc.w + bb.w + r1.y;
        out[node * 32 + lane] = o;
    } else {
        __half2* d = (__half2*)(g_aggh + node * 128 + lane * 4);
        d[0] = __floats2half2_rn(acc.x, acc.y);
        d[1] = __floats2half2_rn(acc.z, acc.w);
    }
}

// ================= FP16 tensor-core fused double-GEMM (M=128 per CTA) =================
#define M_TILE 128
#define SA_H 264
#define SB_H 72
#define SA_HALFS (M_TILE * SA_H)
#define SB_HALFS (256 * SB_H)
#define SMEM_BYTES ((SA_HALFS + 2 * SB_HALFS) * 2)

__device__ __forceinline__ void cp16h(__half* dst, const __half* src) {
    uint32_t sa = (uint32_t)__cvta_generic_to_shared(dst);
    asm volatile("cp.async.ca.shared.global [%0], [%1], 16;" :: "r"(sa), "l"(src));
}
__device__ __forceinline__ void cp_commit() { asm volatile("cp.async.commit_group;"); }
__device__ __forceinline__ void cp_wait0()  { asm volatile("cp.async.wait_group 0;"); }

__device__ __forceinline__ void load_chunkB(__half* buf, const __half* Wg, int kc, int tid) {
#pragma unroll
    for (int i = 0; i < 8; i++) {
        int idx = tid + i * 256;
        int n = idx >> 3, c8 = idx & 7;
        cp16h(buf + n * SB_H + c8 * 8, Wg + n * 256 + kc * 64 + c8 * 8);
    }
}

__device__ __forceinline__ void mma_f16(float* d, uint32_t a0, uint32_t a1, uint32_t a2,
                                        uint32_t a3, uint32_t b0, uint32_t b1) {
    asm volatile(
        "mma.sync.aligned.m16n8k16.row.col.f32.f16.f16.f32 "
        "{%0,%1,%2,%3}, {%4,%5,%6,%7}, {%8,%9}, {%0,%1,%2,%3};"
        : "+f"(d[0]), "+f"(d[1]), "+f"(d[2]), "+f"(d[3])
        : "r"(a0), "r"(a1), "r"(a2), "r"(a3), "r"(b0), "r"(b1));
}

// one 256-K fp16 GEMM: acc += A(128x256 smem) @ Wg(256n x 256k, row=n)^T
__device__ __forceinline__ void gemm_fp16(const __half* A, const __half* Wg, const __half* WgNext,
                                          __half* sB0, __half* sB1,
                                          float acc[8][4][4], int tid, int lane, int n_base) {
    __half* sb[2] = {sB0, sB1};
    for (int kc = 0; kc < 4; kc++) {
        cp_wait0();
        __syncthreads();
        if (kc < 3)      { load_chunkB(sb[(kc + 1) & 1], Wg, kc + 1, tid); cp_commit(); }
        else if (WgNext) { load_chunkB(sb[0], WgNext, 0, tid); cp_commit(); }
        const __half* B = sb[kc & 1];
#pragma unroll
        for (int ksl = 0; ksl < 4; ksl++) {
            uint32_t bf[4][2];
#pragma unroll
            for (int np = 0; np < 2; np++) {
                int n = n_base + np * 16 + ((lane >> 4) << 3) + (lane & 7);
                int kl = ksl * 16 + ((lane >> 3) & 1) * 8;
                uint32_t ad = (uint32_t)__cvta_generic_to_shared(B + n * SB_H + kl);
                asm volatile("ldmatrix.sync.aligned.m8n8.x4.shared.b16 {%0,%1,%2,%3}, [%4];"
                             : "=r"(bf[np * 2][0]), "=r"(bf[np * 2][1]),
                               "=r"(bf[np * 2 + 1][0]), "=r"(bf[np * 2 + 1][1]) : "r"(ad));
            }
#pragma unroll
            for (int mt = 0; mt < 8; mt++) {
                int m = mt * 16 + (lane & 15);
                int kk = kc * 64 + ksl * 16 + (lane >> 4) * 8;
                uint32_t ad = (uint32_t)__cvta_generic_to_shared(A + m * SA_H + kk);
                uint32_t a0, a1, a2, a3;
                asm volatile("ldmatrix.sync.aligned.m8n8.x4.shared.b16 {%0,%1,%2,%3}, [%4];"
                             : "=r"(a0), "=r"(a1), "=r"(a2), "=r"(a3) : "r"(ad));
#pragma unroll
                for (int nt = 0; nt < 4; nt++)
                    mma_f16(acc[mt][nt], a0, a1, a2, a3, bf[nt][0], bf[nt][1]);
            }
        }
    }
}

__global__ __launch_bounds__(256, 1) void gemm_mma_h(const float* __restrict__ b1) {
    extern __shared__ __half smem_h[];
    __half* sA  = smem_h;
    __half* sB0 = smem_h + SA_HALFS;
    __half* sB1 = sB0 + SB_HALFS;

    int tid = threadIdx.x, lane = tid & 31, warp = tid >> 5;
    int node0 = blockIdx.x * M_TILE;
    int n_base = warp * 32;

    load_chunkB(sB0, g_W1h, 0, tid);
    // stage A = [mean1 || x]: 128 nodes x 32 col-groups = 4096 16B units
#pragma unroll
    for (int i = 0; i < 16; i++) {
        int idx = tid + i * 256;
        int n = idx >> 5, c8 = idx & 31;
        int node = node0 + n;
        if (node >= N_NODES) node = N_NODES - 1;
        const __half* src = (c8 < 16) ? (g_aggh + node * 128 + c8 * 8)
                                      : (g_xh  + node * 128 + (c8 - 16) * 8);
        cp16h(sA + n * SA_H + c8 * 8, src);
    }
    cp_commit();

    float acc[8][4][4];
#pragma unroll
    for (int a = 0; a < 8; a++)
#pragma unroll
        for (int b = 0; b < 4; b++)
#pragma unroll
            for (int c = 0; c < 4; c++) acc[a][b][c] = 0.f;

    gemm_fp16(sA, g_W1h, g_W2h, sB0, sB1, acc, tid, lane, n_base);

    __syncthreads();

#pragma unroll
    for (int mt = 0; mt < 8; mt++) {
        int row = mt * 16 + (lane >> 2);
#pragma unroll
        for (int nt = 0; nt < 4; nt++) {
            int col = n_base + nt * 8 + (lane & 3) * 2;
            float bb0 = __ldg(b1 + col), bb1 = __ldg(b1 + col + 1);
            *(__half2*)(sA + row * SA_H + col) =
                __floats2half2_rn(fmaxf(acc[mt][nt][0] + bb0, 0.f),
                                  fmaxf(acc[mt][nt][1] + bb1, 0.f));
            *(__half2*)(sA + (row + 8) * SA_H + col) =
                __floats2half2_rn(fmaxf(acc[mt][nt][2] + bb0, 0.f),
                                  fmaxf(acc[mt][nt][3] + bb1, 0.f));
            acc[mt][nt][0] = acc[mt][nt][1] = acc[mt][nt][2] = acc[mt][nt][3] = 0.f;
        }
    }

    gemm_fp16(sA, g_W2h, nullptr, sB0, sB1, acc, tid, lane, n_base);

    // store p (cols<128) and r2 (cols>=128) as fp16
#pragma unroll
    for (int mt = 0; mt < 8; mt++) {
        int row = mt * 16 + (lane >> 2);
#pragma unroll
        for (int nt = 0; nt < 4; nt++) {
            int col = n_base + nt * 8 + (lane & 3) * 2;
            int node = node0 + row;
            __half* base = (col < 128) ? g_ph : g_r2h;
            int cc = col & 127;
            if (node < N_NODES)
                *(__half2*)(base + node * 128 + cc) =
                    __floats2half2_rn(acc[mt][nt][0], acc[mt][nt][1]);
            if (node + 8 < N_NODES)
                *(__half2*)(base + (node + 8) * 128 + cc) =
                    __floats2half2_rn(acc[mt][nt][2], acc[mt][nt][3]);
        }
    }
}

extern "C" void kernel_launch(void* const* d_in, const int* in_sizes, int n_in,
                              void* d_out, int out_size) {
    const float4* x   = (const float4*)d_in[0];
    const int*    ei  = (const int*)d_in[1];
    const float*  W1l = (const float*)d_in[2];
    const float*  b1  = (const float*)d_in[3];
    const float*  W1r = (const float*)d_in[4];
    const float*  W2l = (const float*)d_in[5];
    const float*  b2  = (const float*)d_in[6];
    const float*  W2r = (const float*)d_in[7];
    int E = in_sizes[1] / 2;
    int prep_total = N_NODES * 32 + 256 * 256 + E;

    cudaFuncSetAttribute(gemm_mma_h, cudaFuncAttributeMaxDynamicSharedMemorySize, SMEM_BYTES);

    prep_all<<<(prep_total + 255) / 256, 256>>>(x, W1l, W1r, W2l, W2r, ei, E);
    scan_all<<<NB_SCAN, 1024>>>(E);
    fill_kernel<<<(E + 255) / 256, 256>>>(ei, E);
    agg_gather<0><<<(N_NODES + 7) / 8, 256>>>(nullptr, nullptr);
    gemm_mma_h<<<(N_NODES + M_TILE - 1) / M_TILE, 256, SMEM_BYTES>>>(b1);
    agg_gather<1><<<(N_NODES + 7) / 8, 256>>>(b2, (float4*)d_out);
}